// round 1
// baseline (speedup 1.0000x reference)
#include <cuda_runtime.h>

// MMD loss, fused:
//   result = (1/4096^2) * sum_{a,b in [0,8192)^2} s_a*s_b * sum_{i=0..4} exp(-L2(a,b)/(bw*2^i))
// with bw = (sum L2)/(n^2-n)/4, computed in closed form:
//   sum L2 = 2n*sum_a||x_a||^2 - 2*||sum_a x_a||^2
// and the 5-kernel sum collapsed to u + u^2 + u^4 + u^8 + u^16, u = exp(-L2/(16 bw)).

#define N_TOTAL 8192
#define HALF_N  4096
#define D       64
#define TILE    128
#define NT      (N_TOTAL / TILE)        // 64 tiles per dim
#define NBLOCKS (NT * (NT + 1) / 2)     // 2080 upper-triangle tiles
#define SMEM_MAIN (2 * D * TILE * 4 + 256 * 8)  // As + Bs + double red[256]

__device__ float  g_sq[N_TOTAL];
__device__ float  g_colsum[D];
__device__ double g_sumsq;
__device__ double g_acc;
__device__ float  g_negc;

// ---------------------------------------------------------------------------
// Kernel 0: zero accumulators (graph is replayed; must reset every launch)
// ---------------------------------------------------------------------------
__global__ void k_init() {
    int t = threadIdx.x;
    if (t < D) g_colsum[t] = 0.0f;
    if (t == 0) { g_sumsq = 0.0; g_acc = 0.0; }
}

// ---------------------------------------------------------------------------
// Kernel 1: per-row squared norms, column sums, total squared sum.
// One warp per row: lane l handles cols l and l+32.
// Grid: 32 blocks x 256 threads, 256 rows per block.
// ---------------------------------------------------------------------------
__global__ void k_rows(const float* __restrict__ src, const float* __restrict__ tgt) {
    __shared__ float  sc[D];
    __shared__ double sred[8];
    int t = threadIdx.x, lane = t & 31, w = t >> 5;
    if (t < D) sc[t] = 0.0f;
    __syncthreads();

    int rowBase = blockIdx.x * 256 + w * 32;
    float c0 = 0.0f, c1 = 0.0f, ssq = 0.0f;
    for (int i = 0; i < 32; ++i) {
        int r = rowBase + i;
        const float* row = (r < HALF_N) ? (src + (size_t)r * D)
                                        : (tgt + (size_t)(r - HALF_N) * D);
        float v0 = row[lane], v1 = row[lane + 32];
        c0 += v0; c1 += v1;
        float s = v0 * v0 + v1 * v1;
        ssq += s;
        #pragma unroll
        for (int o = 16; o; o >>= 1) s += __shfl_xor_sync(0xffffffffu, s, o);
        if (lane == 0) g_sq[r] = s;
    }
    atomicAdd(&sc[lane], c0);
    atomicAdd(&sc[lane + 32], c1);
    #pragma unroll
    for (int o = 16; o; o >>= 1) ssq += __shfl_xor_sync(0xffffffffu, ssq, o);
    if (lane == 0) sred[w] = (double)ssq;
    __syncthreads();
    if (t < D) atomicAdd(&g_colsum[t], sc[t]);
    if (t == 0) {
        double s = 0.0;
        #pragma unroll
        for (int i = 0; i < 8; ++i) s += sred[i];
        atomicAdd(&g_sumsq, s);
    }
}

// ---------------------------------------------------------------------------
// Kernel 2: bandwidth -> exp scale factor (single thread)
// ---------------------------------------------------------------------------
__global__ void k_bw() {
    double norm2 = 0.0;
    for (int j = 0; j < D; ++j) {
        double c = (double)g_colsum[j];
        norm2 += c * c;
    }
    double n = (double)N_TOTAL;
    double sumL2 = 2.0 * n * g_sumsq - 2.0 * norm2;
    double bw = sumL2 / (n * n - n);
    bw *= 0.25;                               // / KERNEL_MUL^(KERNEL_NUM//2) = /4
    g_negc = (float)(-1.0 / (16.0 * bw));     // u = exp(L2 * negc)
}

// ---------------------------------------------------------------------------
// Kernel 3: fused pairwise tile GEMM + kernel-sum + signed reduction.
// Upper block-triangle only; off-diagonal tiles weighted x2.
// 128x128 tile, 256 threads, 8x8 micro-tile per thread, K=64 loaded once.
// ---------------------------------------------------------------------------
__global__ void __launch_bounds__(256)
k_main(const float* __restrict__ src, const float* __restrict__ tgt) {
    extern __shared__ float smem[];
    float*  As  = smem;                    // [D][TILE] k-major
    float*  Bs  = smem + D * TILE;         // [D][TILE]
    double* red = (double*)(smem + 2 * D * TILE);

    // decode upper-triangle (br, bc) from linear block index (uniform, cheap)
    int lin = blockIdx.x, br = 0, rem = lin;
    while (rem >= NT - br) { rem -= NT - br; ++br; }
    int bc = br + rem;

    int t = threadIdx.x;

    // cooperative load of both tiles, transposed into k-major smem
    #pragma unroll
    for (int side = 0; side < 2; ++side) {
        int   rowBase = (side == 0 ? br : bc) * TILE;
        float* S      = (side == 0 ? As : Bs);
        #pragma unroll
        for (int it = 0; it < 8; ++it) {
            int idx = it * 256 + t;        // 0..2047 float4 chunks
            int r   = idx & (TILE - 1);    // row within tile
            int kg  = idx >> 7;            // float4 group 0..15
            int gr  = rowBase + r;
            const float* rp = (gr < HALF_N) ? (src + (size_t)gr * D)
                                            : (tgt + (size_t)(gr - HALF_N) * D);
            float4 v = *(const float4*)(rp + kg * 4);
            S[(kg * 4 + 0) * TILE + r] = v.x;
            S[(kg * 4 + 1) * TILE + r] = v.y;
            S[(kg * 4 + 2) * TILE + r] = v.z;
            S[(kg * 4 + 3) * TILE + r] = v.w;
        }
    }
    __syncthreads();

    int tx = t & 15, ty = t >> 4;          // 16x16 thread grid
    float acc[8][8];
    #pragma unroll
    for (int i = 0; i < 8; ++i)
        #pragma unroll
        for (int j = 0; j < 8; ++j) acc[i][j] = 0.0f;

    #pragma unroll 4
    for (int k = 0; k < D; ++k) {
        float aF[8], bF[8];
        *(float4*)&aF[0] = *(const float4*)&As[k * TILE + ty * 8];
        *(float4*)&aF[4] = *(const float4*)&As[k * TILE + ty * 8 + 4];
        *(float4*)&bF[0] = *(const float4*)&Bs[k * TILE + tx * 8];
        *(float4*)&bF[4] = *(const float4*)&Bs[k * TILE + tx * 8 + 4];
        #pragma unroll
        for (int i = 0; i < 8; ++i)
            #pragma unroll
            for (int j = 0; j < 8; ++j)
                acc[i][j] += aF[i] * bF[j];
    }

    // epilogue: L2 -> 5-kernel sum via u^{1,2,4,8,16}
    float sqa[8], sqb[8];
    #pragma unroll
    for (int i = 0; i < 8; ++i) sqa[i] = __ldg(&g_sq[br * TILE + ty * 8 + i]);
    #pragma unroll
    for (int j = 0; j < 8; ++j) sqb[j] = __ldg(&g_sq[bc * TILE + tx * 8 + j]);
    float negc = g_negc;

    float part = 0.0f;
    #pragma unroll
    for (int i = 0; i < 8; ++i) {
        #pragma unroll
        for (int j = 0; j < 8; ++j) {
            float L2v = sqa[i] + sqb[j] - 2.0f * acc[i][j];
            float u   = __expf(L2v * negc);
            float u2 = u * u, u4 = u2 * u2, u8 = u4 * u4, u16 = u8 * u8;
            part += u + u2 + u4 + u8 + u16;
        }
    }

    float sA = (br < NT / 2) ? 1.0f : -1.0f;
    float sB = (bc < NT / 2) ? 1.0f : -1.0f;
    float wt = (br == bc) ? 1.0f : 2.0f;     // symmetry: count (a,b)&(b,a)
    red[t] = (double)part * (double)(sA * sB * wt);
    __syncthreads();
    #pragma unroll
    for (int s = 128; s; s >>= 1) {
        if (t < s) red[t] += red[t + s];
        __syncthreads();
    }
    if (t == 0) atomicAdd(&g_acc, red[0]);
}

// ---------------------------------------------------------------------------
// Kernel 4: finalize
// ---------------------------------------------------------------------------
__global__ void k_final(float* out) {
    out[0] = (float)(g_acc / ((double)HALF_N * (double)HALF_N));
}

extern "C" void kernel_launch(void* const* d_in, const int* in_sizes, int n_in,
                              void* d_out, int out_size) {
    const float* src = (const float*)d_in[0];
    const float* tgt = (const float*)d_in[1];
    float* out = (float*)d_out;
    (void)in_sizes; (void)n_in; (void)out_size;

    cudaFuncSetAttribute(k_main, cudaFuncAttributeMaxDynamicSharedMemorySize, SMEM_MAIN);

    k_init<<<1, 64>>>();
    k_rows<<<N_TOTAL / 256, 256>>>(src, tgt);
    k_bw<<<1, 1>>>();
    k_main<<<NBLOCKS, 256, SMEM_MAIN>>>(src, tgt);
    k_final<<<1, 1>>>(out);
}

// round 4
// speedup vs baseline: 1.9743x; 1.9743x over previous
#include <cuda_runtime.h>
#include <cuda_bf16.h>
#include <cstdint>

// MMD loss via mma.sync (HMMA) bf16-split pairwise GEMM + fused Gaussian epilogue.
//   result = (1/4096^2) * sum_{a,b} s_a s_b * (u + u^2 + u^4 + u^8 + u^16),
//   u = exp(-L2(a,b)/(16*bw)),  bw closed-form from norms/colsums.
// Upper block-triangle only (off-diag tiles weighted x2).
// a.b ~= ah.bh + al.bh + ah.bl  with rows stored as [hi(64)|lo(64)] bf16.

#define N_TOTAL 8192
#define HALF_N  4096
#define D       64
#define TILE    128
#define NT      64
#define NTILES  2080          // NT*(NT+1)/2
#define GRID_MAIN 296

#define STRIDE  136           // bf16 per smem tile row (pad: 68 words % 32 = 4)
// dynamic smem layout (bytes)
#define A_OFF     0                   // 128 * 272 = 34816
#define B_OFF     34816
#define SQA_OFF   69632               // 128 floats
#define SQB_OFF   70144
#define RED_OFF   70656               // 256 doubles
#define SMEM_TOTAL 72704

__device__ __nv_bfloat16 g_buf[(size_t)N_TOTAL * 128];   // [hi(64) | lo(64)] per row
__device__ float  g_sq[N_TOTAL];
__device__ float  g_colsum[D];
__device__ double g_sumsq;
__device__ double g_acc;
__device__ float  g_negc;   // -log2(e)/(16*bw)

__device__ __forceinline__ float ex2f(float x) {
    float y; asm("ex2.approx.ftz.f32 %0, %1;" : "=f"(y) : "f"(x)); return y;
}
__device__ __forceinline__ void mma16816(float* c, uint32_t a0, uint32_t a1,
                                         uint32_t a2, uint32_t a3,
                                         uint32_t b0, uint32_t b1) {
    asm volatile(
        "mma.sync.aligned.m16n8k16.row.col.f32.bf16.bf16.f32 "
        "{%0,%1,%2,%3}, {%4,%5,%6,%7}, {%8,%9}, {%0,%1,%2,%3};"
        : "+f"(c[0]), "+f"(c[1]), "+f"(c[2]), "+f"(c[3])
        : "r"(a0), "r"(a1), "r"(a2), "r"(a3), "r"(b0), "r"(b1));
}

// ---------------------------------------------------------------------------
// Kernel 0: zero accumulators (graph replay resets)
// ---------------------------------------------------------------------------
__global__ void k_init() {
    int t = threadIdx.x;
    if (t < D) g_colsum[t] = 0.0f;
    if (t == 0) { g_sumsq = 0.0; g_acc = 0.0; }
}

// ---------------------------------------------------------------------------
// Kernel 1: row norms, column sums, total sq sum, + bf16 hi/lo split buffer.
// One warp per 32 rows; lane l handles cols l and l+32.
// ---------------------------------------------------------------------------
__global__ void k_rows(const float* __restrict__ src, const float* __restrict__ tgt) {
    __shared__ float  sc[D];
    __shared__ double sred[8];
    int t = threadIdx.x, lane = t & 31, w = t >> 5;
    if (t < D) sc[t] = 0.0f;
    __syncthreads();

    int rowBase = blockIdx.x * 256 + w * 32;
    float c0 = 0.0f, c1 = 0.0f, ssq = 0.0f;
    for (int i = 0; i < 32; ++i) {
        int r = rowBase + i;
        const float* row = (r < HALF_N) ? (src + (size_t)r * D)
                                        : (tgt + (size_t)(r - HALF_N) * D);
        float v0 = row[lane], v1 = row[lane + 32];
        c0 += v0; c1 += v1;

        __nv_bfloat16 h0 = __float2bfloat16_rn(v0);
        __nv_bfloat16 h1 = __float2bfloat16_rn(v1);
        __nv_bfloat16 l0 = __float2bfloat16_rn(v0 - __bfloat162float(h0));
        __nv_bfloat16 l1 = __float2bfloat16_rn(v1 - __bfloat162float(h1));
        size_t base = (size_t)r * 128;
        g_buf[base + lane]           = h0;  g_buf[base + lane + 32]      = h1;
        g_buf[base + 64 + lane]      = l0;  g_buf[base + 64 + lane + 32] = l1;

        float s = v0 * v0 + v1 * v1;
        ssq += s;
        #pragma unroll
        for (int o = 16; o; o >>= 1) s += __shfl_xor_sync(0xffffffffu, s, o);
        if (lane == 0) g_sq[r] = s;
    }
    atomicAdd(&sc[lane], c0);
    atomicAdd(&sc[lane + 32], c1);
    #pragma unroll
    for (int o = 16; o; o >>= 1) ssq += __shfl_xor_sync(0xffffffffu, ssq, o);
    if (lane == 0) sred[w] = (double)ssq;
    __syncthreads();
    if (t < D) atomicAdd(&g_colsum[t], sc[t]);
    if (t == 0) {
        double s = 0.0;
        #pragma unroll
        for (int i = 0; i < 8; ++i) s += sred[i];
        atomicAdd(&g_sumsq, s);
    }
}

// ---------------------------------------------------------------------------
// Kernel 2: bandwidth -> exp2 scale (single thread)
// ---------------------------------------------------------------------------
__global__ void k_bw() {
    double norm2 = 0.0;
    for (int j = 0; j < D; ++j) { double c = (double)g_colsum[j]; norm2 += c * c; }
    double n = (double)N_TOTAL;
    double sumL2 = 2.0 * n * g_sumsq - 2.0 * norm2;
    double bw = sumL2 / (n * n - n);
    bw *= 0.25;                                           // / KERNEL_MUL^(KERNEL_NUM//2)
    g_negc = (float)(-1.4426950408889634 / (16.0 * bw));  // exp2 scale
}

// ---------------------------------------------------------------------------
// Kernel 3: persistent HMMA tile loop. 8 warps = 2x4 grid of 64x32 warp tiles.
// ---------------------------------------------------------------------------
__global__ void __launch_bounds__(256, 2)
k_main() {
    extern __shared__ char smem[];
    __nv_bfloat16* As  = (__nv_bfloat16*)(smem + A_OFF);
    __nv_bfloat16* Bs  = (__nv_bfloat16*)(smem + B_OFF);
    float*  sqA = (float*)(smem + SQA_OFF);
    float*  sqB = (float*)(smem + SQB_OFF);
    double* red = (double*)(smem + RED_OFF);

    int t = threadIdx.x, lane = t & 31, w = t >> 5;
    int wr = w >> 2, wc = w & 3;           // warp tile: rows wr*64, cols wc*32
    int g  = lane >> 2, tq = lane & 3;     // fragment group / quad

    float negc = g_negc;
    double acc_d = 0.0;

    for (int tile = blockIdx.x; tile < NTILES; tile += GRID_MAIN) {
        int br = 0, rem = tile;
        while (rem >= NT - br) { rem -= NT - br; ++br; }
        int bc = br + rem;

        __syncthreads();   // previous tile's smem reads complete

        // ---- cooperative tile load: g_buf rows -> padded smem (coalesced 16B)
        #pragma unroll
        for (int side = 0; side < 2; ++side) {
            int rowBase = (side ? bc : br) * TILE;
            char* S = smem + (side ? B_OFF : A_OFF);
            #pragma unroll
            for (int it = 0; it < 8; ++it) {
                int idx = it * 256 + t;            // [0, 2048)
                int row = idx >> 4, c = idx & 15;  // 16 x 16B chunks per row
                uint4 v = *(const uint4*)(g_buf + ((size_t)(rowBase + row) * 128 + c * 8));
                *(uint4*)(S + row * (STRIDE * 2) + c * 16) = v;
            }
        }
        if (t < 128)      sqA[t]       = g_sq[br * TILE + t];
        else              sqB[t - 128] = g_sq[bc * TILE + (t - 128)];
        __syncthreads();

        // ---- MMA: 3 passes (hi.hi, lo.hi, hi.lo) x 4 K-steps of 16
        float acc[4][4][4];
        #pragma unroll
        for (int mi = 0; mi < 4; ++mi)
            #pragma unroll
            for (int ni = 0; ni < 4; ++ni)
                #pragma unroll
                for (int q = 0; q < 4; ++q) acc[mi][ni][q] = 0.0f;

        const int kAoff[3] = {0, 64, 0};
        const int kBoff[3] = {0, 0, 64};
        #pragma unroll
        for (int pass = 0; pass < 3; ++pass) {
            #pragma unroll
            for (int ks = 0; ks < 4; ++ks) {
                int ka = kAoff[pass] + ks * 16 + tq * 2;
                int kb = kBoff[pass] + ks * 16 + tq * 2;
                uint32_t bf[4][2];
                #pragma unroll
                for (int ni = 0; ni < 4; ++ni) {
                    const __nv_bfloat16* bp = Bs + (wc * 32 + ni * 8 + g) * STRIDE + kb;
                    bf[ni][0] = *(const uint32_t*)bp;
                    bf[ni][1] = *(const uint32_t*)(bp + 8);
                }
                #pragma unroll
                for (int mi = 0; mi < 4; ++mi) {
                    const __nv_bfloat16* ap = As + (wr * 64 + mi * 16 + g) * STRIDE + ka;
                    uint32_t a0 = *(const uint32_t*)ap;
                    uint32_t a1 = *(const uint32_t*)(ap + 8 * STRIDE);
                    uint32_t a2 = *(const uint32_t*)(ap + 8);
                    uint32_t a3 = *(const uint32_t*)(ap + 8 * STRIDE + 8);
                    #pragma unroll
                    for (int ni = 0; ni < 4; ++ni)
                        mma16816(acc[mi][ni], a0, a1, a2, a3, bf[ni][0], bf[ni][1]);
                }
            }
        }

        // ---- fused epilogue from accumulator registers
        float sa[4][2], sb[4][2];
        #pragma unroll
        for (int mi = 0; mi < 4; ++mi) {
            sa[mi][0] = sqA[wr * 64 + mi * 16 + g];
            sa[mi][1] = sqA[wr * 64 + mi * 16 + g + 8];
        }
        #pragma unroll
        for (int ni = 0; ni < 4; ++ni) {
            sb[ni][0] = sqB[wc * 32 + ni * 8 + tq * 2];
            sb[ni][1] = sqB[wc * 32 + ni * 8 + tq * 2 + 1];
        }

        float part = 0.0f;
        #pragma unroll
        for (int mi = 0; mi < 4; ++mi) {
            #pragma unroll
            for (int ni = 0; ni < 4; ++ni) {
                #pragma unroll
                for (int q = 0; q < 4; ++q) {
                    float s  = sa[mi][q >> 1] + sb[ni][q & 1];
                    float L2 = fmaf(-2.0f, acc[mi][ni][q], s);
                    float u  = ex2f(L2 * negc);
                    float u2 = u * u, u4 = u2 * u2, u8 = u4 * u4, u16 = u8 * u8;
                    part += (u + u2) + (u4 + u8) + u16;
                }
            }
        }

        float sA = (br < NT / 2) ? 1.0f : -1.0f;
        float sB = (bc < NT / 2) ? 1.0f : -1.0f;
        float wt = (br == bc) ? 1.0f : 2.0f;
        acc_d += (double)part * (double)(sA * sB * wt);
    }

    // ---- block reduction + single atomic
    __syncthreads();
    red[t] = acc_d;
    __syncthreads();
    #pragma unroll
    for (int s = 128; s; s >>= 1) {
        if (t < s) red[t] += red[t + s];
        __syncthreads();
    }
    if (t == 0) atomicAdd(&g_acc, red[0]);
}

// ---------------------------------------------------------------------------
// Kernel 4: finalize
// ---------------------------------------------------------------------------
__global__ void k_final(float* out) {
    out[0] = (float)(g_acc / ((double)HALF_N * (double)HALF_N));
}

extern "C" void kernel_launch(void* const* d_in, const int* in_sizes, int n_in,
                              void* d_out, int out_size) {
    const float* src = (const float*)d_in[0];
    const float* tgt = (const float*)d_in[1];
    float* out = (float*)d_out;
    (void)in_sizes; (void)n_in; (void)out_size;

    cudaFuncSetAttribute(k_main, cudaFuncAttributeMaxDynamicSharedMemorySize, SMEM_TOTAL);

    k_init<<<1, 64>>>();
    k_rows<<<N_TOTAL / 256, 256>>>(src, tgt);
    k_bw<<<1, 1>>>();
    k_main<<<GRID_MAIN, 256, SMEM_TOTAL>>>();
    k_final<<<1, 1>>>(out);
}

// round 5
// speedup vs baseline: 3.1958x; 1.6187x over previous
#include <cuda_runtime.h>
#include <cuda_bf16.h>
#include <cstdint>

// MMD loss via mma.sync (HMMA) bf16-split pairwise GEMM + fused Gaussian epilogue.
//   result = (1/4096^2) * sum_{a,b} s_a s_b * (u + u^2 + u^4 + u^8 + u^16),
//   u = exp(-L2(a,b)/(16*bw)),  bw closed-form from norms/colsums.
// Upper block-triangle only (off-diag tiles weighted x2).
// a.b ~= ah.bh + al.bh + ah.bl  with rows stored as [hi(64)|lo(64)] bf16.

#define N_TOTAL 8192
#define HALF_N  4096
#define D       64
#define TILE    128
#define NT      64
#define NTILES  2080
#define GRID_MAIN 296

#define STRIDE  136           // bf16 per smem row (68 words % 32 = 4 -> LDSM conflict-free)
#define ROWB    (STRIDE * 2)  // 272 bytes
// dynamic smem layout (bytes)
#define A_OFF     0                   // 128 * 272 = 34816
#define B_OFF     34816
#define SQA_OFF   69632               // 128 floats
#define SQB_OFF   70144
#define RED_OFF   70656               // 256 doubles
#define SMEM_TOTAL 72704

__device__ __nv_bfloat16 g_buf[(size_t)N_TOTAL * 128];   // [hi(64) | lo(64)] per row
__device__ float  g_sq[N_TOTAL];
__device__ float  g_colsum[D];
__device__ double g_sumsq;
__device__ double g_acc;
__device__ int    g_done;

// ---------------- helpers ----------------
__device__ __forceinline__ uint32_t smem_u32(const void* p) {
    uint32_t a;
    asm("{ .reg .u64 t; cvta.to.shared.u64 t, %1; cvt.u32.u64 %0, t; }" : "=r"(a) : "l"(p));
    return a;
}
__device__ __forceinline__ float ex2f(float x) {
    float y; asm("ex2.approx.ftz.f32 %0, %1;" : "=f"(y) : "f"(x)); return y;
}
__device__ __forceinline__ uint64_t pack2(float lo, float hi) {
    uint64_t r; asm("mov.b64 %0, {%1, %2};" : "=l"(r) : "f"(lo), "f"(hi)); return r;
}
__device__ __forceinline__ void unpack2(uint64_t v, float& lo, float& hi) {
    asm("mov.b64 {%0, %1}, %2;" : "=f"(lo), "=f"(hi) : "l"(v));
}
__device__ __forceinline__ uint64_t fma2(uint64_t a, uint64_t b, uint64_t c) {
    uint64_t d; asm("fma.rn.f32x2 %0, %1, %2, %3;" : "=l"(d) : "l"(a), "l"(b), "l"(c)); return d;
}
__device__ __forceinline__ uint64_t mul2(uint64_t a, uint64_t b) {
    uint64_t d; asm("mul.rn.f32x2 %0, %1, %2;" : "=l"(d) : "l"(a), "l"(b)); return d;
}
__device__ __forceinline__ uint64_t add2(uint64_t a, uint64_t b) {
    uint64_t d; asm("add.rn.f32x2 %0, %1, %2;" : "=l"(d) : "l"(a), "l"(b)); return d;
}
__device__ __forceinline__ void ldsm_x4(uint32_t addr, uint32_t* r) {
    asm volatile("ldmatrix.sync.aligned.m8n8.x4.shared.b16 {%0,%1,%2,%3}, [%4];"
        : "=r"(r[0]), "=r"(r[1]), "=r"(r[2]), "=r"(r[3]) : "r"(addr));
}
__device__ __forceinline__ void mma16816(float* c, const uint32_t* a, uint32_t b0, uint32_t b1) {
    asm volatile(
        "mma.sync.aligned.m16n8k16.row.col.f32.bf16.bf16.f32 "
        "{%0,%1,%2,%3}, {%4,%5,%6,%7}, {%8,%9}, {%0,%1,%2,%3};"
        : "+f"(c[0]), "+f"(c[1]), "+f"(c[2]), "+f"(c[3])
        : "r"(a[0]), "r"(a[1]), "r"(a[2]), "r"(a[3]), "r"(b0), "r"(b1));
}
__device__ __forceinline__ void cp16(uint32_t saddr, const void* gaddr) {
    asm volatile("cp.async.cg.shared.global [%0], [%1], 16;" :: "r"(saddr), "l"(gaddr));
}

// ---------------------------------------------------------------------------
// Kernel 0: zero accumulators (graph replay resets)
// ---------------------------------------------------------------------------
__global__ void k_init() {
    int t = threadIdx.x;
    if (t < D) g_colsum[t] = 0.0f;
    if (t == 0) { g_sumsq = 0.0; g_acc = 0.0; g_done = 0; }
}

// ---------------------------------------------------------------------------
// Kernel 1: row norms, column sums, total sq sum, + bf16 hi/lo split buffer.
// 64 blocks x 256; warp handles 16 rows; lane handles cols 2l, 2l+1.
// ---------------------------------------------------------------------------
__global__ void k_rows(const float* __restrict__ src, const float* __restrict__ tgt) {
    __shared__ float  sc[D];
    __shared__ double sred[8];
    int t = threadIdx.x, lane = t & 31, w = t >> 5;
    if (t < D) sc[t] = 0.0f;
    __syncthreads();

    int rowBase = blockIdx.x * 128 + w * 16;
    float c0 = 0.0f, c1 = 0.0f, ssq = 0.0f;
    for (int i = 0; i < 16; ++i) {
        int r = rowBase + i;
        const float* row = (r < HALF_N) ? (src + (size_t)r * D)
                                        : (tgt + (size_t)(r - HALF_N) * D);
        float2 v = ((const float2*)row)[lane];
        c0 += v.x; c1 += v.y;

        __nv_bfloat16 h0 = __float2bfloat16_rn(v.x);
        __nv_bfloat16 h1 = __float2bfloat16_rn(v.y);
        __nv_bfloat16 l0 = __float2bfloat16_rn(v.x - __bfloat162float(h0));
        __nv_bfloat16 l1 = __float2bfloat16_rn(v.y - __bfloat162float(h1));
        size_t base = (size_t)r * 128;
        __nv_bfloat162 hp; hp.x = h0; hp.y = h1;
        __nv_bfloat162 lp; lp.x = l0; lp.y = l1;
        *(__nv_bfloat162*)(g_buf + base + 2 * lane)      = hp;
        *(__nv_bfloat162*)(g_buf + base + 64 + 2 * lane) = lp;

        float s = v.x * v.x + v.y * v.y;
        ssq += s;
        #pragma unroll
        for (int o = 16; o; o >>= 1) s += __shfl_xor_sync(0xffffffffu, s, o);
        if (lane == 0) g_sq[r] = s;
    }
    atomicAdd(&sc[2 * lane],     c0);
    atomicAdd(&sc[2 * lane + 1], c1);
    #pragma unroll
    for (int o = 16; o; o >>= 1) ssq += __shfl_xor_sync(0xffffffffu, ssq, o);
    if (lane == 0) sred[w] = (double)ssq;
    __syncthreads();
    if (t < D) atomicAdd(&g_colsum[t], sc[t]);
    if (t == 0) {
        double s = 0.0;
        #pragma unroll
        for (int i = 0; i < 8; ++i) s += sred[i];
        atomicAdd(&g_sumsq, s);
    }
}

// ---------------------------------------------------------------------------
// Kernel 2: persistent HMMA tile loop. 8 warps = 2x4 grid of 64x32 warp tiles.
// ldmatrix fragments, cp.async tile loads, packed f32x2 epilogue.
// Also computes bandwidth per-block and finalizes via completion counter.
// ---------------------------------------------------------------------------
__global__ void __launch_bounds__(256, 2)
k_main(float* __restrict__ out) {
    extern __shared__ char smem[];
    uint32_t sbase = smem_u32(smem);
    float*  sqA = (float*)(smem + SQA_OFF);
    float*  sqB = (float*)(smem + SQB_OFF);
    double* red = (double*)(smem + RED_OFF);
    __shared__ float s_negc;

    int t = threadIdx.x, lane = t & 31, w = t >> 5;
    int wr = w >> 2, wc = w & 3;            // warp tile: rows wr*64, cols wc*32
    int g  = lane >> 2, tq = lane & 3;

    if (t == 0) {
        double norm2 = 0.0;
        for (int j = 0; j < D; ++j) { double c = (double)g_colsum[j]; norm2 += c * c; }
        double n = (double)N_TOTAL;
        double sumL2 = 2.0 * n * g_sumsq - 2.0 * norm2;
        double bw = sumL2 / (n * n - n) * 0.25;
        s_negc = (float)(-1.4426950408889634 / (16.0 * bw));
    }
    __syncthreads();
    float negc = s_negc;
    uint64_t NC2 = pack2(negc, negc);
    uint64_t M2  = pack2(-2.0f, -2.0f);

    // per-lane ldmatrix base addresses
    uint32_t aAddr = sbase + A_OFF + (uint32_t)((wr * 64 + (lane & 15)) * ROWB + (lane >> 4) * 16);
    uint32_t bAddr = sbase + B_OFF + (uint32_t)((wc * 32 + ((lane >> 4) << 3) + (lane & 7)) * ROWB
                                                + ((lane >> 3) & 1) * 16);
    double acc_d = 0.0;

    for (int tile = blockIdx.x; tile < NTILES; tile += GRID_MAIN) {
        int br = 0, rem = tile;
        while (rem >= NT - br) { rem -= NT - br; ++br; }
        int bc = br + rem;

        __syncthreads();   // previous tile's smem reads complete

        // ---- cp.async tile loads: g_buf rows -> padded smem
        {
            int row = t >> 1, cpair = (t & 1) * 8;   // two 16B chunks per row-half? no:
        }
        #pragma unroll
        for (int side = 0; side < 2; ++side) {
            int rowBase = (side ? bc : br) * TILE;
            uint32_t S = sbase + (side ? B_OFF : A_OFF);
            #pragma unroll
            for (int it = 0; it < 8; ++it) {
                int idx = it * 256 + t;            // [0, 2048)
                int row = idx >> 4, c = idx & 15;  // 16 x 16B chunks per row
                cp16(S + row * ROWB + c * 16,
                     g_buf + ((size_t)(rowBase + row) * 128 + c * 8));
            }
        }
        asm volatile("cp.async.commit_group;");
        if (t < 128)      sqA[t]       = g_sq[br * TILE + t];
        else              sqB[t - 128] = g_sq[bc * TILE + (t - 128)];
        asm volatile("cp.async.wait_group 0;" ::: "memory");
        __syncthreads();

        // ---- MMA: 3 passes (hi.hi, lo.hi, hi.lo) x 4 K-steps of 16
        float acc[4][4][4];
        #pragma unroll
        for (int mi = 0; mi < 4; ++mi)
            #pragma unroll
            for (int ni = 0; ni < 4; ++ni)
                #pragma unroll
                for (int q = 0; q < 4; ++q) acc[mi][ni][q] = 0.0f;

        const int kAoff[3] = {0, 64, 0};
        const int kBoff[3] = {0, 0, 64};
        #pragma unroll
        for (int pass = 0; pass < 3; ++pass) {
            #pragma unroll
            for (int ks = 0; ks < 4; ++ks) {
                uint32_t ka = (uint32_t)(kAoff[pass] + ks * 16) * 2;
                uint32_t kb = (uint32_t)(kBoff[pass] + ks * 16) * 2;
                uint32_t bf0[4], bf1[4];
                ldsm_x4(bAddr + kb, bf0);                   // n-frags 0,1
                ldsm_x4(bAddr + kb + 16 * ROWB, bf1);       // n-frags 2,3
                #pragma unroll
                for (int mi = 0; mi < 4; ++mi) {
                    uint32_t af[4];
                    ldsm_x4(aAddr + ka + (uint32_t)(mi * 16 * ROWB), af);
                    mma16816(acc[mi][0], af, bf0[0], bf0[1]);
                    mma16816(acc[mi][1], af, bf0[2], bf0[3]);
                    mma16816(acc[mi][2], af, bf1[0], bf1[1]);
                    mma16816(acc[mi][3], af, bf1[2], bf1[3]);
                }
            }
        }

        // ---- packed f32x2 epilogue from accumulator registers
        uint64_t sa0p[4], sa1p[4], sbp[4];
        #pragma unroll
        for (int mi = 0; mi < 4; ++mi) {
            float s0 = sqA[wr * 64 + mi * 16 + g];
            float s1 = sqA[wr * 64 + mi * 16 + g + 8];
            sa0p[mi] = pack2(s0, s0);
            sa1p[mi] = pack2(s1, s1);
        }
        #pragma unroll
        for (int ni = 0; ni < 4; ++ni)
            sbp[ni] = pack2(sqB[wc * 32 + ni * 8 + tq * 2],
                            sqB[wc * 32 + ni * 8 + tq * 2 + 1]);

        uint64_t partp = pack2(0.0f, 0.0f);
        #pragma unroll
        for (int mi = 0; mi < 4; ++mi) {
            #pragma unroll
            for (int ni = 0; ni < 4; ++ni) {
                #pragma unroll
                for (int half = 0; half < 2; ++half) {
                    uint64_t ap = pack2(acc[mi][ni][half * 2], acc[mi][ni][half * 2 + 1]);
                    uint64_t sp = add2(half ? sa1p[mi] : sa0p[mi], sbp[ni]);
                    uint64_t xp = mul2(fma2(ap, M2, sp), NC2);
                    float xl, xh;
                    unpack2(xp, xl, xh);
                    uint64_t u  = pack2(ex2f(xl), ex2f(xh));
                    uint64_t u2 = mul2(u, u);
                    uint64_t u4 = mul2(u2, u2);
                    uint64_t u8 = mul2(u4, u4);
                    uint64_t u16 = mul2(u8, u8);
                    uint64_t sgrp = add2(add2(u, u2), add2(u4, u8));
                    partp = add2(partp, add2(sgrp, u16));
                }
            }
        }
        float pl, ph;
        unpack2(partp, pl, ph);
        float part = pl + ph;

        float sA = (br < NT / 2) ? 1.0f : -1.0f;
        float sB = (bc < NT / 2) ? 1.0f : -1.0f;
        float wt = (br == bc) ? 1.0f : 2.0f;
        acc_d += (double)part * (double)(sA * sB * wt);
    }

    // ---- block reduction + single atomic + finalize
    __syncthreads();
    red[t] = acc_d;
    __syncthreads();
    #pragma unroll
    for (int s = 128; s; s >>= 1) {
        if (t < s) red[t] += red[t + s];
        __syncthreads();
    }
    if (t == 0) {
        atomicAdd(&g_acc, red[0]);
        __threadfence();
        int prev = atomicAdd(&g_done, 1);
        if (prev == GRID_MAIN - 1) {
            __threadfence();
            out[0] = (float)(g_acc / ((double)HALF_N * (double)HALF_N));
        }
    }
}

extern "C" void kernel_launch(void* const* d_in, const int* in_sizes, int n_in,
                              void* d_out, int out_size) {
    const float* src = (const float*)d_in[0];
    const float* tgt = (const float*)d_in[1];
    float* out = (float*)d_out;
    (void)in_sizes; (void)n_in; (void)out_size;

    cudaFuncSetAttribute(k_main, cudaFuncAttributeMaxDynamicSharedMemorySize, SMEM_TOTAL);

    k_init<<<1, 64>>>();
    k_rows<<<N_TOTAL / 128, 256>>>(src, tgt);
    k_main<<<GRID_MAIN, 256, SMEM_TOTAL>>>(out);
}

// round 7
// speedup vs baseline: 3.2695x; 1.0230x over previous
#include <cuda_runtime.h>
#include <cuda_bf16.h>
#include <cstdint>

// MMD loss, single persistent kernel:
//   phase 1: bf16 hi/lo split + row norms + colsums (grid-strided)
//   grid barrier (296 blocks == exactly resident)
//   phase 2: HMMA pairwise tile GEMM + fused Gaussian epilogue, prefetch-pipelined
//   result = (1/4096^2) * sum s_a s_b (u+u^2+u^4+u^8+u^16), u = exp(-L2/(16bw))

#define N_TOTAL 8192
#define HALF_N  4096
#define D       64
#define TILE    128
#define NT      64
#define NTILES  2080
#define GRID_MAIN 296
#define NFULL   2072            // = 296*7 tiles distributed evenly
#define NLEFT   8               // tiles 2072..2079 -> 16 half-units for blocks 0..15

#define STRIDE  136             // bf16 per smem row (68 words % 32 = 4 -> LDSM conflict-free)
#define ROWB    272
// dynamic smem layout (bytes)
#define A_OFF     0             // 128*272 = 34816
#define B_OFF     34816
#define NSA_OFF   69632         // float[2][128] (negc * sqA, double-buffered)
#define NSB_OFF   70656         // float[2][128]
#define RED_OFF   71680         // double[256]
#define SMEM_TOTAL 73728

__device__ __nv_bfloat16 g_buf[(size_t)N_TOTAL * 128];   // [hi(64)|lo(64)] per row
__device__ float  g_sq[N_TOTAL];
__device__ float  g_colsum[D];
__device__ double g_sumsq;
__device__ double g_acc;
__device__ int    g_bar;
__device__ int    g_done;

// ---------------- helpers ----------------
__device__ __forceinline__ uint32_t smem_u32(const void* p) {
    uint32_t a;
    asm("{ .reg .u64 t; cvta.to.shared.u64 t, %1; cvt.u32.u64 %0, t; }" : "=r"(a) : "l"(p));
    return a;
}
__device__ __forceinline__ float ex2f(float x) {
    float y; asm("ex2.approx.ftz.f32 %0, %1;" : "=f"(y) : "f"(x)); return y;
}
__device__ __forceinline__ uint64_t pack2(float lo, float hi) {
    uint64_t r; asm("mov.b64 %0, {%1, %2};" : "=l"(r) : "f"(lo), "f"(hi)); return r;
}
__device__ __forceinline__ void unpack2(uint64_t v, float& lo, float& hi) {
    asm("mov.b64 {%0, %1}, %2;" : "=f"(lo), "=f"(hi) : "l"(v));
}
__device__ __forceinline__ uint64_t fma2(uint64_t a, uint64_t b, uint64_t c) {
    uint64_t d; asm("fma.rn.f32x2 %0, %1, %2, %3;" : "=l"(d) : "l"(a), "l"(b), "l"(c)); return d;
}
__device__ __forceinline__ uint64_t mul2(uint64_t a, uint64_t b) {
    uint64_t d; asm("mul.rn.f32x2 %0, %1, %2;" : "=l"(d) : "l"(a), "l"(b)); return d;
}
__device__ __forceinline__ uint64_t add2(uint64_t a, uint64_t b) {
    uint64_t d; asm("add.rn.f32x2 %0, %1, %2;" : "=l"(d) : "l"(a), "l"(b)); return d;
}
__device__ __forceinline__ void ldsm_x4(uint32_t addr, uint32_t* r) {
    asm volatile("ldmatrix.sync.aligned.m8n8.x4.shared.b16 {%0,%1,%2,%3}, [%4];"
        : "=r"(r[0]), "=r"(r[1]), "=r"(r[2]), "=r"(r[3]) : "r"(addr));
}
__device__ __forceinline__ void mma16816(float* c, const uint32_t* a, uint32_t b0, uint32_t b1) {
    asm volatile(
        "mma.sync.aligned.m16n8k16.row.col.f32.bf16.bf16.f32 "
        "{%0,%1,%2,%3}, {%4,%5,%6,%7}, {%8,%9}, {%0,%1,%2,%3};"
        : "+f"(c[0]), "+f"(c[1]), "+f"(c[2]), "+f"(c[3])
        : "r"(a[0]), "r"(a[1]), "r"(a[2]), "r"(a[3]), "r"(b0), "r"(b1));
}
__device__ __forceinline__ void cp16(uint32_t saddr, const void* gaddr) {
    asm volatile("cp.async.cg.shared.global [%0], [%1], 16;" :: "r"(saddr), "l"(gaddr));
}

// ---------------- MMA worker: 3 passes (hh, lh, hl), NI = n-frags per warp ----
template<int NI>
__device__ __forceinline__ void tile_mma(uint32_t sbase, uint32_t aAddr,
                                         int lane, int w, float acc[4][4][4]) {
    int wc = w & 3;
    uint32_t bAddr = sbase + B_OFF
        + (uint32_t)(wc * 8 * NI + ((lane >> 4) << 3) + (lane & 7)) * ROWB
        + (uint32_t)((lane >> 3) & 1) * 16;

    #pragma unroll
    for (int mi = 0; mi < 4; ++mi)
        #pragma unroll
        for (int ni = 0; ni < NI; ++ni)
            #pragma unroll
            for (int q = 0; q < 4; ++q) acc[mi][ni][q] = 0.0f;

    const int kAoff[3] = {0, 64, 0};
    const int kBoff[3] = {0, 0, 64};
    #pragma unroll
    for (int pass = 0; pass < 3; ++pass) {
        #pragma unroll
        for (int ks = 0; ks < 4; ++ks) {
            uint32_t ka = (uint32_t)(kAoff[pass] + ks * 16) * 2;
            uint32_t kb = (uint32_t)(kBoff[pass] + ks * 16) * 2;
            uint32_t bf0[4], bf1[4];
            ldsm_x4(bAddr + kb, bf0);
            if (NI == 4) ldsm_x4(bAddr + kb + 16 * ROWB, bf1);
            #pragma unroll
            for (int mi = 0; mi < 4; ++mi) {
                uint32_t af[4];
                ldsm_x4(aAddr + ka + (uint32_t)(mi * 16 * ROWB), af);
                mma16816(acc[mi][0], af, bf0[0], bf0[1]);
                mma16816(acc[mi][1], af, bf0[2], bf0[3]);
                if (NI == 4) {
                    mma16816(acc[mi][2], af, bf1[0], bf1[1]);
                    mma16816(acc[mi][3], af, bf1[2], bf1[3]);
                }
            }
        }
    }
}

// ---------------- epilogue: L2 -> u+u^2+u^4+u^8+u^16, packed f32x2 ------------
template<int NI>
__device__ __forceinline__ float tile_epi(const float acc[4][4][4],
                                          const float* nsAb, const float* nsBb,
                                          int lane, int w, uint64_t M2NC) {
    int wr = w >> 2, wc = w & 3;
    int g = lane >> 2, tq = lane & 3;
    uint64_t partp = pack2(0.0f, 0.0f);
    #pragma unroll
    for (int mi = 0; mi < 4; ++mi) {
        float na0 = nsAb[wr * 64 + mi * 16 + g];
        float na1 = nsAb[wr * 64 + mi * 16 + g + 8];
        uint64_t na0p = pack2(na0, na0), na1p = pack2(na1, na1);
        #pragma unroll
        for (int ni = 0; ni < NI; ++ni) {
            int cb = wc * 8 * NI + ni * 8 + tq * 2;
            uint64_t nbp = pack2(nsBb[cb], nsBb[cb + 1]);
            #pragma unroll
            for (int h = 0; h < 2; ++h) {
                uint64_t ap = pack2(acc[mi][ni][2 * h], acc[mi][ni][2 * h + 1]);
                uint64_t xp = fma2(ap, M2NC, add2(h ? na1p : na0p, nbp));
                float xl, xh; unpack2(xp, xl, xh);
                uint64_t u  = pack2(ex2f(xl), ex2f(xh));
                uint64_t u2 = mul2(u, u);
                uint64_t u4 = mul2(u2, u2);
                uint64_t u8 = mul2(u4, u4);
                partp = add2(partp, add2(add2(u, u2), add2(u4, u8)));
                partp = fma2(u8, u8, partp);            // + u^16
            }
        }
    }
    float pl, ph; unpack2(partp, pl, ph);
    return pl + ph;
}

// ---------------------------------------------------------------------------
__global__ void __launch_bounds__(256, 2)
k_all(const float* __restrict__ src, const float* __restrict__ tgt,
      float* __restrict__ out) {
    extern __shared__ char smem[];
    uint32_t sbase = smem_u32(smem);
    float*  nsA = (float*)(smem + NSA_OFF);
    float*  nsB = (float*)(smem + NSB_OFF);
    double* red = (double*)(smem + RED_OFF);
    __shared__ float s_negc;

    int t = threadIdx.x, lane = t & 31, w = t >> 5;
    int b = blockIdx.x;

    // ================= phase 1: row preprocessing =================
    {
        float*  sc   = (float*)(smem + A_OFF);
        double* sred = (double*)(smem + A_OFF + 256);
        if (t < D) sc[t] = 0.0f;
        __syncthreads();

        float c0 = 0.0f, c1 = 0.0f, ssq = 0.0f;
        for (int r = b * 8 + w; r < N_TOTAL; r += GRID_MAIN * 8) {
            const float* row = (r < HALF_N) ? src + (size_t)r * D
                                            : tgt + (size_t)(r - HALF_N) * D;
            float2 v = ((const float2*)row)[lane];
            c0 += v.x; c1 += v.y;
            __nv_bfloat16 h0 = __float2bfloat16_rn(v.x);
            __nv_bfloat16 h1 = __float2bfloat16_rn(v.y);
            __nv_bfloat16 l0 = __float2bfloat16_rn(v.x - __bfloat162float(h0));
            __nv_bfloat16 l1 = __float2bfloat16_rn(v.y - __bfloat162float(h1));
            size_t base = (size_t)r * 128;
            __nv_bfloat162 hp; hp.x = h0; hp.y = h1;
            __nv_bfloat162 lp; lp.x = l0; lp.y = l1;
            *(__nv_bfloat162*)(g_buf + base + 2 * lane)      = hp;
            *(__nv_bfloat162*)(g_buf + base + 64 + 2 * lane) = lp;
            float s = v.x * v.x + v.y * v.y;
            ssq += s;
            #pragma unroll
            for (int o = 16; o; o >>= 1) s += __shfl_xor_sync(0xffffffffu, s, o);
            if (lane == 0) g_sq[r] = s;
        }
        atomicAdd(&sc[2 * lane],     c0);
        atomicAdd(&sc[2 * lane + 1], c1);
        #pragma unroll
        for (int o = 16; o; o >>= 1) ssq += __shfl_xor_sync(0xffffffffu, ssq, o);
        if (lane == 0) sred[w] = (double)ssq;
        __syncthreads();
        if (t < D) atomicAdd(&g_colsum[t], sc[t]);
        if (t == 0) {
            double s = 0.0;
            #pragma unroll
            for (int i = 0; i < 8; ++i) s += sred[i];
            atomicAdd(&g_sumsq, s);
        }
    }

    // ================= grid barrier (all 296 blocks resident) =================
    __threadfence();
    __syncthreads();
    if (t == 0) {
        atomicAdd(&g_bar, 1);
        while (atomicAdd(&g_bar, 0) < GRID_MAIN) __nanosleep(64);
        __threadfence();
    }
    __syncthreads();

    if (t == 0) {
        double norm2 = 0.0;
        for (int j = 0; j < D; ++j) { double c = (double)g_colsum[j]; norm2 += c * c; }
        double n = (double)N_TOTAL;
        double sumL2 = 2.0 * n * g_sumsq - 2.0 * norm2;
        double bw = sumL2 / (n * n - n) * 0.25;
        s_negc = (float)(-1.4426950408889634 / (16.0 * bw));
    }
    __syncthreads();
    float negc = s_negc;
    uint64_t M2NC = pack2(-2.0f * negc, -2.0f * negc);

    // ================= phase 2: tile loop, prefetch-pipelined =================
    uint32_t aAddr = sbase + A_OFF
        + (uint32_t)((w >> 2) * 64 + (lane & 15)) * ROWB + (uint32_t)(lane >> 4) * 16;

    int nU = 7 + ((b < 2 * NLEFT) ? 1 : 0);

    auto decode = [&](int i, int& br, int& bc, int& colBase, int& nB) {
        int u;
        if (i < 7) { u = b + GRID_MAIN * i; colBase = 0;            nB = 128; }
        else       { u = NFULL + (b >> 1);  colBase = (b & 1) * 64; nB = 64;  }
        int rem = u; br = 0;
        while (rem >= NT - br) { rem -= NT - br; ++br; }
        bc = br + rem;
    };
    auto issue_load = [&](int br, int bRow0, int nB, int buf) {
        #pragma unroll
        for (int it = 0; it < 8; ++it) {
            int idx = it * 256 + t;
            int row = idx >> 4, c = idx & 15;
            cp16(sbase + A_OFF + row * ROWB + c * 16,
                 g_buf + (((size_t)(br * TILE + row)) << 7) + c * 8);
        }
        for (int idx = t; idx < nB * 16; idx += 256) {
            int row = idx >> 4, c = idx & 15;
            cp16(sbase + B_OFF + row * ROWB + c * 16,
                 g_buf + (((size_t)(bRow0 + row)) << 7) + c * 8);
        }
        asm volatile("cp.async.commit_group;");
        if (t < 128)             nsA[buf * 128 + t]       = negc * g_sq[br * TILE + t];
        else if (t - 128 < nB)   nsB[buf * 128 + t - 128] = negc * g_sq[bRow0 + t - 128];
    };

    double acc_d = 0.0;
    int br, bc, colBase, nB;
    decode(0, br, bc, colBase, nB);
    issue_load(br, bc * TILE + colBase, nB, 0);

    for (int i = 0; i < nU; ++i) {
        int cbr = br, cbc = bc;
        asm volatile("cp.async.wait_group 0;" ::: "memory");
        __syncthreads();

        float acc[4][4][4];
        if (i < 7) tile_mma<4>(sbase, aAddr, lane, w, acc);
        else       tile_mma<2>(sbase, aAddr, lane, w, acc);
        __syncthreads();                   // all smem-tile reads done

        if (i + 1 < nU) {                  // prefetch next tile during epilogue
            decode(i + 1, br, bc, colBase, nB);
            issue_load(br, bc * TILE + colBase, nB, (i + 1) & 1);
        }

        const float* nsAb = nsA + (i & 1) * 128;
        const float* nsBb = nsB + (i & 1) * 128;
        float part = (i < 7) ? tile_epi<4>(acc, nsAb, nsBb, lane, w, M2NC)
                             : tile_epi<2>(acc, nsAb, nsBb, lane, w, M2NC);

        float sA = (cbr < NT / 2) ? 1.0f : -1.0f;
        float sB = (cbc < NT / 2) ? 1.0f : -1.0f;
        float wt = (cbr == cbc) ? 1.0f : 2.0f;
        acc_d += (double)part * (double)(sA * sB * wt);
    }

    // ================= reduction + finalize + replay reset =================
    __syncthreads();
    red[t] = acc_d;
    __syncthreads();
    #pragma unroll
    for (int s = 128; s; s >>= 1) {
        if (t < s) red[t] += red[t + s];
        __syncthreads();
    }
    if (t == 0) {
        atomicAdd(&g_acc, red[0]);
        __threadfence();
        int prev = atomicAdd(&g_done, 1);
        if (prev == GRID_MAIN - 1) {
            __threadfence();
            double total = atomicAdd(&g_acc, 0.0);
            out[0] = (float)(total / ((double)HALF_N * (double)HALF_N));
            // reset for next graph replay
            g_acc = 0.0; g_sumsq = 0.0; g_bar = 0; g_done = 0;
            for (int j = 0; j < D; ++j) g_colsum[j] = 0.0f;
            __threadfence();
        }
    }
}

extern "C" void kernel_launch(void* const* d_in, const int* in_sizes, int n_in,
                              void* d_out, int out_size) {
    const float* src = (const float*)d_in[0];
    const float* tgt = (const float*)d_in[1];
    float* out = (float*)d_out;
    (void)in_sizes; (void)n_in; (void)out_size;

    cudaFuncSetAttribute(k_all, cudaFuncAttributeMaxDynamicSharedMemorySize, SMEM_TOTAL);
    k_all<<<GRID_MAIN, 256, SMEM_TOTAL>>>(src, tgt, out);
}

// round 9
// speedup vs baseline: 4.6014x; 1.4074x over previous
#include <cuda_runtime.h>
#include <cuda_bf16.h>
#include <cstdint>

// MMD loss, single persistent kernel:
//   phase 1: bf16 hi/lo split + row norms + colsums (grid-strided)
//   grid barrier (296 blocks == exactly resident)
//   phase 2: HMMA pairwise tile GEMM (2-pass bf16 split: a.b ~= (ah+al).bh)
//            + fused Gaussian epilogue, prefetch-pipelined
//   result = (1/4096^2) * sum s_a s_b (u+u^2+u^4+u^8+u^16), u = exp(-L2/(16bw))

#define N_TOTAL 8192
#define HALF_N  4096
#define D       64
#define TILE    128
#define NT      64
#define NTILES  2080
#define GRID_MAIN 296
#define NFULL   2072            // = 296*7 tiles distributed evenly
#define NLEFT   8               // tiles 2072..2079 -> 16 half-units for blocks 0..15

#define STRIDE  136             // bf16 per smem row (68 words % 32 = 4 -> LDSM conflict-free)
#define ROWB    272
// dynamic smem layout (bytes)
#define A_OFF     0             // 128*272 = 34816
#define B_OFF     34816
#define NSA_OFF   69632         // float[2][128] (negc * sqA, double-buffered)
#define NSB_OFF   70656         // float[2][128]
#define RED_OFF   71680         // double[256]
#define SMEM_TOTAL 73728

__device__ __nv_bfloat16 g_buf[(size_t)N_TOTAL * 128];   // [hi(64)|lo(64)] per row
__device__ float  g_sq[N_TOTAL];
__device__ float  g_colsum[D];
__device__ double g_sumsq;
__device__ double g_acc;
__device__ int    g_bar;
__device__ int    g_done;

// ---------------- helpers ----------------
__device__ __forceinline__ uint32_t smem_u32(const void* p) {
    uint32_t a;
    asm("{ .reg .u64 t; cvta.to.shared.u64 t, %1; cvt.u32.u64 %0, t; }" : "=r"(a) : "l"(p));
    return a;
}
__device__ __forceinline__ float ex2f(float x) {
    float y; asm("ex2.approx.ftz.f32 %0, %1;" : "=f"(y) : "f"(x)); return y;
}
__device__ __forceinline__ uint64_t pack2(float lo, float hi) {
    uint64_t r; asm("mov.b64 %0, {%1, %2};" : "=l"(r) : "f"(lo), "f"(hi)); return r;
}
__device__ __forceinline__ void unpack2(uint64_t v, float& lo, float& hi) {
    asm("mov.b64 {%0, %1}, %2;" : "=f"(lo), "=f"(hi) : "l"(v));
}
__device__ __forceinline__ uint64_t fma2(uint64_t a, uint64_t b, uint64_t c) {
    uint64_t d; asm("fma.rn.f32x2 %0, %1, %2, %3;" : "=l"(d) : "l"(a), "l"(b), "l"(c)); return d;
}
__device__ __forceinline__ uint64_t mul2(uint64_t a, uint64_t b) {
    uint64_t d; asm("mul.rn.f32x2 %0, %1, %2;" : "=l"(d) : "l"(a), "l"(b)); return d;
}
__device__ __forceinline__ uint64_t add2(uint64_t a, uint64_t b) {
    uint64_t d; asm("add.rn.f32x2 %0, %1, %2;" : "=l"(d) : "l"(a), "l"(b)); return d;
}
__device__ __forceinline__ void ldsm_x4(uint32_t addr, uint32_t* r) {
    asm volatile("ldmatrix.sync.aligned.m8n8.x4.shared.b16 {%0,%1,%2,%3}, [%4];"
        : "=r"(r[0]), "=r"(r[1]), "=r"(r[2]), "=r"(r[3]) : "r"(addr));
}
__device__ __forceinline__ void mma16816(float* c, const uint32_t* a, uint32_t b0, uint32_t b1) {
    asm volatile(
        "mma.sync.aligned.m16n8k16.row.col.f32.bf16.bf16.f32 "
        "{%0,%1,%2,%3}, {%4,%5,%6,%7}, {%8,%9}, {%0,%1,%2,%3};"
        : "+f"(c[0]), "+f"(c[1]), "+f"(c[2]), "+f"(c[3])
        : "r"(a[0]), "r"(a[1]), "r"(a[2]), "r"(a[3]), "r"(b0), "r"(b1));
}
__device__ __forceinline__ void cp16(uint32_t saddr, const void* gaddr) {
    asm volatile("cp.async.cg.shared.global [%0], [%1], 16;" :: "r"(saddr), "l"(gaddr));
}

// ---------------- MMA worker: 2 passes fused per K-step (ah.bh + al.bh) -------
// B fragments loaded once per K-step and reused by both A passes.
template<int NI>
__device__ __forceinline__ void tile_mma(uint32_t sbase, uint32_t aAddr,
                                         int lane, int w, float acc[4][4][4]) {
    int wc = w & 3;
    uint32_t bAddr = sbase + B_OFF
        + (uint32_t)(wc * 8 * NI + ((lane >> 4) << 3) + (lane & 7)) * ROWB
        + (uint32_t)((lane >> 3) & 1) * 16;

    #pragma unroll
    for (int mi = 0; mi < 4; ++mi)
        #pragma unroll
        for (int ni = 0; ni < NI; ++ni)
            #pragma unroll
            for (int q = 0; q < 4; ++q) acc[mi][ni][q] = 0.0f;

    #pragma unroll
    for (int ks = 0; ks < 4; ++ks) {
        uint32_t ka = (uint32_t)(ks * 16) * 2;       // hi window; lo window = +128B
        uint32_t bf0[4], bf1[4];
        ldsm_x4(bAddr + ka, bf0);
        if (NI == 4) ldsm_x4(bAddr + ka + 16 * ROWB, bf1);
        #pragma unroll
        for (int mi = 0; mi < 4; ++mi) {
            uint32_t afh[4], afl[4];
            uint32_t base = aAddr + ka + (uint32_t)(mi * 16 * ROWB);
            ldsm_x4(base, afh);
            ldsm_x4(base + 128, afl);                // +64 bf16 = lo half
            mma16816(acc[mi][0], afh, bf0[0], bf0[1]);
            mma16816(acc[mi][1], afh, bf0[2], bf0[3]);
            if (NI == 4) {
                mma16816(acc[mi][2], afh, bf1[0], bf1[1]);
                mma16816(acc[mi][3], afh, bf1[2], bf1[3]);
            }
            mma16816(acc[mi][0], afl, bf0[0], bf0[1]);
            mma16816(acc[mi][1], afl, bf0[2], bf0[3]);
            if (NI == 4) {
                mma16816(acc[mi][2], afl, bf1[0], bf1[1]);
                mma16816(acc[mi][3], afl, bf1[2], bf1[3]);
            }
        }
    }
}

// ---------------- epilogue: L2 -> u+u^2+u^4+u^8+u^16, packed f32x2 ------------
template<int NI>
__device__ __forceinline__ float tile_epi(const float acc[4][4][4],
                                          const float* nsAb, const float* nsBb,
                                          int lane, int w, uint64_t M2NC) {
    int wr = w >> 2, wc = w & 3;
    int g = lane >> 2, tq = lane & 3;
    uint64_t partp = pack2(0.0f, 0.0f);
    #pragma unroll
    for (int mi = 0; mi < 4; ++mi) {
        float na0 = nsAb[wr * 64 + mi * 16 + g];
        float na1 = nsAb[wr * 64 + mi * 16 + g + 8];
        uint64_t na0p = pack2(na0, na0), na1p = pack2(na1, na1);
        #pragma unroll
        for (int ni = 0; ni < NI; ++ni) {
            int cb = wc * 8 * NI + ni * 8 + tq * 2;
            uint64_t nbp = pack2(nsBb[cb], nsBb[cb + 1]);
            #pragma unroll
            for (int h = 0; h < 2; ++h) {
                uint64_t ap = pack2(acc[mi][ni][2 * h], acc[mi][ni][2 * h + 1]);
                uint64_t xp = fma2(ap, M2NC, add2(h ? na1p : na0p, nbp));
                float xl, xh; unpack2(xp, xl, xh);
                uint64_t u  = pack2(ex2f(xl), ex2f(xh));
                uint64_t u2 = mul2(u, u);
                uint64_t u4 = mul2(u2, u2);
                uint64_t u8 = mul2(u4, u4);
                partp = add2(partp, add2(add2(u, u2), add2(u4, u8)));
                partp = fma2(u8, u8, partp);            // + u^16
            }
        }
    }
    float pl, ph; unpack2(partp, pl, ph);
    return pl + ph;
}

// ---------------------------------------------------------------------------
__global__ void __launch_bounds__(256, 2)
k_all(const float* __restrict__ src, const float* __restrict__ tgt,
      float* __restrict__ out) {
    extern __shared__ char smem[];
    uint32_t sbase = smem_u32(smem);
    float*  nsA = (float*)(smem + NSA_OFF);
    float*  nsB = (float*)(smem + NSB_OFF);
    double* red = (double*)(smem + RED_OFF);
    __shared__ float s_negc;

    int t = threadIdx.x, lane = t & 31, w = t >> 5;
    int b = blockIdx.x;

    // ================= phase 1: row preprocessing =================
    {
        float*  sc   = (float*)(smem + A_OFF);
        double* sred = (double*)(smem + A_OFF + 256);
        if (t < D) sc[t] = 0.0f;
        __syncthreads();

        float c0 = 0.0f, c1 = 0.0f, ssq = 0.0f;
        for (int r = b * 8 + w; r < N_TOTAL; r += GRID_MAIN * 8) {
            const float* row = (r < HALF_N) ? src + (size_t)r * D
                                            : tgt + (size_t)(r - HALF_N) * D;
            float2 v = ((const float2*)row)[lane];
            c0 += v.x; c1 += v.y;
            __nv_bfloat16 h0 = __float2bfloat16_rn(v.x);
            __nv_bfloat16 h1 = __float2bfloat16_rn(v.y);
            __nv_bfloat16 l0 = __float2bfloat16_rn(v.x - __bfloat162float(h0));
            __nv_bfloat16 l1 = __float2bfloat16_rn(v.y - __bfloat162float(h1));
            size_t base = (size_t)r * 128;
            __nv_bfloat162 hp; hp.x = h0; hp.y = h1;
            __nv_bfloat162 lp; lp.x = l0; lp.y = l1;
            *(__nv_bfloat162*)(g_buf + base + 2 * lane)      = hp;
            *(__nv_bfloat162*)(g_buf + base + 64 + 2 * lane) = lp;
            float s = v.x * v.x + v.y * v.y;
            ssq += s;
            #pragma unroll
            for (int o = 16; o; o >>= 1) s += __shfl_xor_sync(0xffffffffu, s, o);
            if (lane == 0) g_sq[r] = s;
        }
        atomicAdd(&sc[2 * lane],     c0);
        atomicAdd(&sc[2 * lane + 1], c1);
        #pragma unroll
        for (int o = 16; o; o >>= 1) ssq += __shfl_xor_sync(0xffffffffu, ssq, o);
        if (lane == 0) sred[w] = (double)ssq;
        __syncthreads();
        if (t < D) atomicAdd(&g_colsum[t], sc[t]);
        if (t == 0) {
            double s = 0.0;
            #pragma unroll
            for (int i = 0; i < 8; ++i) s += sred[i];
            atomicAdd(&g_sumsq, s);
        }
    }

    // ================= grid barrier (all 296 blocks resident) =================
    __threadfence();
    __syncthreads();
    if (t == 0) {
        atomicAdd(&g_bar, 1);
        while (atomicAdd(&g_bar, 0) < GRID_MAIN) __nanosleep(64);
        __threadfence();
    }
    __syncthreads();

    if (t == 0) {
        double norm2 = 0.0;
        for (int j = 0; j < D; ++j) { double c = (double)g_colsum[j]; norm2 += c * c; }
        double n = (double)N_TOTAL;
        double sumL2 = 2.0 * n * g_sumsq - 2.0 * norm2;
        double bw = sumL2 / (n * n - n) * 0.25;
        s_negc = (float)(-1.4426950408889634 / (16.0 * bw));
    }
    __syncthreads();
    float negc = s_negc;
    uint64_t M2NC = pack2(-2.0f * negc, -2.0f * negc);

    // ================= phase 2: tile loop, prefetch-pipelined =================
    uint32_t aAddr = sbase + A_OFF
        + (uint32_t)((w >> 2) * 64 + (lane & 15)) * ROWB + (uint32_t)(lane >> 4) * 16;

    int nU = 7 + ((b < 2 * NLEFT) ? 1 : 0);

    auto decode = [&](int i, int& br, int& bc, int& colBase, int& nB) {
        int u;
        if (i < 7) { u = b + GRID_MAIN * i; colBase = 0;            nB = 128; }
        else       { u = NFULL + (b >> 1);  colBase = (b & 1) * 64; nB = 64;  }
        int rem = u; br = 0;
        while (rem >= NT - br) { rem -= NT - br; ++br; }
        bc = br + rem;
    };
    auto issue_load = [&](int br, int bRow0, int nB, int buf) {
        #pragma unroll
        for (int it = 0; it < 8; ++it) {
            int idx = it * 256 + t;
            int row = idx >> 4, c = idx & 15;
            cp16(sbase + A_OFF + row * ROWB + c * 16,
                 g_buf + (((size_t)(br * TILE + row)) << 7) + c * 8);
        }
        for (int idx = t; idx < nB * 16; idx += 256) {
            int row = idx >> 4, c = idx & 15;
            cp16(sbase + B_OFF + row * ROWB + c * 16,
                 g_buf + (((size_t)(bRow0 + row)) << 7) + c * 8);
        }
        asm volatile("cp.async.commit_group;");
        if (t < 128)             nsA[buf * 128 + t]       = negc * g_sq[br * TILE + t];
        else if (t - 128 < nB)   nsB[buf * 128 + t - 128] = negc * g_sq[bRow0 + t - 128];
    };

    double acc_d = 0.0;
    int br, bc, colBase, nB;
    decode(0, br, bc, colBase, nB);
    issue_load(br, bc * TILE + colBase, nB, 0);

    for (int i = 0; i < nU; ++i) {
        int cbr = br, cbc = bc;
        asm volatile("cp.async.wait_group 0;" ::: "memory");
        __syncthreads();

        float acc[4][4][4];
        if (i < 7) tile_mma<4>(sbase, aAddr, lane, w, acc);
        else       tile_mma<2>(sbase, aAddr, lane, w, acc);
        __syncthreads();                   // all smem-tile reads done

        if (i + 1 < nU) {                  // prefetch next tile during epilogue
            decode(i + 1, br, bc, colBase, nB);
            issue_load(br, bc * TILE + colBase, nB, (i + 1) & 1);
        }

        const float* nsAb = nsA + (i & 1) * 128;
        const float* nsBb = nsB + (i & 1) * 128;
        float part = (i < 7) ? tile_epi<4>(acc, nsAb, nsBb, lane, w, M2NC)
                             : tile_epi<2>(acc, nsAb, nsBb, lane, w, M2NC);

        float sA = (cbr < NT / 2) ? 1.0f : -1.0f;
        float sB = (cbc < NT / 2) ? 1.0f : -1.0f;
        float wt = (cbr == cbc) ? 1.0f : 2.0f;
        acc_d += (double)part * (double)(sA * sB * wt);
    }

    // ================= reduction + finalize + replay reset =================
    __syncthreads();
    red[t] = acc_d;
    __syncthreads();
    #pragma unroll
    for (int s = 128; s; s >>= 1) {
        if (t < s) red[t] += red[t + s];
        __syncthreads();
    }
    if (t == 0) {
        atomicAdd(&g_acc, red[0]);
        __threadfence();
        int prev = atomicAdd(&g_done, 1);
        if (prev == GRID_MAIN - 1) {
            __threadfence();
            double total = atomicAdd(&g_acc, 0.0);
            out[0] = (float)(total / ((double)HALF_N * (double)HALF_N));
            // reset for next graph replay
            g_acc = 0.0; g_sumsq = 0.0; g_bar = 0; g_done = 0;
            for (int j = 0; j < D; ++j) g_colsum[j] = 0.0f;
            __threadfence();
        }
    }
}

extern "C" void kernel_launch(void* const* d_in, const int* in_sizes, int n_in,
                              void* d_out, int out_size) {
    const float* src = (const float*)d_in[0];
    const float* tgt = (const float*)d_in[1];
    float* out = (float*)d_out;
    (void)in_sizes; (void)n_in; (void)out_size;

    cudaFuncSetAttribute(k_all, cudaFuncAttributeMaxDynamicSharedMemorySize, SMEM_TOTAL);
    k_all<<<GRID_MAIN, 256, SMEM_TOTAL>>>(src, tgt, out);
}